// round 9
// baseline (speedup 1.0000x reference)
#include <cuda_runtime.h>

// DTree_84061099917446 — soft decision tree forward pass.
// N=262144 rows, F=32, depth 8, 255 nodes, 256 leaves, C=1.
//
// R9: attack per-warp serialization (3 flat rounds at ~165us; fma busy is
// already at its 84us floor but issue=52%). Two changes:
//  1) __launch_bounds__(256,3) -> 80-reg budget: +16 regs = exactly one
//     node's W double-buffer, letting ptxas overlap node i+1's loads with
//     node i's EX2->RCP gate chain (the structural ILP was register-starved
//     at 64 regs).
//  2) 16/16 const/smem W split: 4 LDC.128 (literal uniform addresses ->
//     LDCU port) + 4 LDS.128 per node; bias + leaf pairs in const too.
// Still: full compile-time tree unroll, W pre-scaled by -log2(e), gate =
// EX2+FADD+RCP, depth-7 leaf-pair folding, 1 row/thread.

#define F_      32
#define NODES_  255
#define N_ROWS  262144
#define TPB     256
#define LOG2E_F 1.4426950408889634f

typedef unsigned long long u64;
typedef unsigned int u32;

// All constant-bank data in one blob (single D2D publish per launch).
struct CData {
    ulonglong2 w16[NODES_ * 4];   // features 0..15, packed f32x2 pairs, 16320B
    u64        b2[NODES_];        // packed (+log2e*c, 0)                 2040B
    float2     pr[128];           // (clsR, clsL - clsR)                  1024B
};
__constant__ CData cD;

// Staging + smem sources (scratch via __device__ globals — no allocation).
__device__ CData g_stage;
__device__ __align__(16) float g_Wsm[NODES_ * 16];   // features 16..31

// ---------------------------------------------------------------------------
__device__ __forceinline__ u64 pk2(float lo, float hi) {
    u64 r;
    asm("mov.b64 %0, {%1, %2};" : "=l"(r) : "f"(lo), "f"(hi));
    return r;
}

// ---------------------------------------------------------------------------
// Prologue: one block, 256 threads; thread t<255 handles node t serially.
// ---------------------------------------------------------------------------
__global__ void prep_kernel(const float* __restrict__ fi,
                            const float* __restrict__ fs,
                            const float* __restrict__ cls) {
    int t = threadIdx.x;
    if (t < NODES_) {
        float bias = 0.0f;
        float wp[F_];
        #pragma unroll
        for (int f = 0; f < F_; ++f) {
            int idx = t * F_ + f;
            float w = fmaxf(fi[idx], 0.0f);
            float s = 1.0f / (1.0f + expf(-fs[idx]));
            bias += w * s;
            wp[f] = -LOG2E_F * w;
        }
        // features 0..15 -> const staging (4x ulonglong2 per node)
        #pragma unroll
        for (int q = 0; q < 4; ++q) {
            ulonglong2 v;
            v.x = pk2(wp[4 * q],     wp[4 * q + 1]);
            v.y = pk2(wp[4 * q + 2], wp[4 * q + 3]);
            g_stage.w16[t * 4 + q] = v;
        }
        // features 16..31 -> smem source
        #pragma unroll
        for (int f = 16; f < F_; ++f) g_Wsm[t * 16 + (f - 16)] = wp[f];
        g_stage.b2[t] = pk2(LOG2E_F * bias, 0.0f);
    }
    if (t < 128) {
        float lv = cls[2 * t];
        float rv = cls[2 * t + 1];
        g_stage.pr[t] = make_float2(rv, lv - rv);
    }
}

// ---------------------------------------------------------------------------
// Packed f32x2 / gate helpers.
// ---------------------------------------------------------------------------
__device__ __forceinline__ u64 ffma2(u64 a, u64 b, u64 c) {
    u64 d;
    asm("fma.rn.f32x2 %0, %1, %2, %3;" : "=l"(d) : "l"(a), "l"(b), "l"(c));
    return d;
}

__device__ __forceinline__ float psum(u64 a, u64 b) {
    u64 s;
    asm("add.rn.f32x2 %0, %1, %2;" : "=l"(s) : "l"(a), "l"(b));
    float lo, hi;
    asm("mov.b64 {%0, %1}, %2;" : "=f"(lo), "=f"(hi) : "l"(s));
    return lo + hi;
}

// y = -log2e * z  ->  g = sigmoid(z) = 1 / (1 + 2^y)
__device__ __forceinline__ float fgate(float y) {
    float e, g;
    asm("ex2.approx.f32 %0, %1;" : "=f"(e) : "f"(y));
    float d = 1.0f + e;
    asm("rcp.approx.f32 %0, %1;" : "=f"(g) : "f"(d));
    return g;
}

// ---------------------------------------------------------------------------
// Compile-time-unrolled DFS. NODE literal everywhere -> const reads have
// literal (uniform) addresses; smem reads have immediate offsets.
// ---------------------------------------------------------------------------
template<int DEPTH, int NODE>
__device__ __forceinline__ void subtree(const float* __restrict__ sW,
                                        const u64 (&xa)[16],
                                        float prod, float& acc) {
    u64 A0 = cD.b2[NODE];              // init = (+log2e*c, 0), LDC.64
    u64 A1 = 0ull;
    // const part: features 0..15 (xa[0..7]), 4x LDC.128
    #pragma unroll
    for (int q = 0; q < 4; ++q) {
        ulonglong2 w = cD.w16[NODE * 4 + q];
        A0 = ffma2(xa[2 * q],     w.x, A0);
        A1 = ffma2(xa[2 * q + 1], w.y, A1);
    }
    // smem part: features 16..31 (xa[8..15]), 4x LDS.128
    {
        const ulonglong2* wp =
            reinterpret_cast<const ulonglong2*>(sW + NODE * 16);
        #pragma unroll
        for (int i = 0; i < 4; ++i) {
            ulonglong2 w = wp[i];
            A0 = ffma2(xa[8 + 2 * i], w.x, A0);
            A1 = ffma2(xa[9 + 2 * i], w.y, A1);
        }
    }
    float g = fgate(psum(A0, A1));

    if constexpr (DEPTH == 7) {
        float2 pr = cD.pr[NODE - 127];            // (clsR, clsL - clsR)
        acc = fmaf(prod, fmaf(g, pr.y, pr.x), acc);
    } else {
        float r = fmaf(-prod, g, prod);           // prod*(1-g)
        subtree<DEPTH + 1, 2 * NODE + 1>(sW, xa, prod * g, acc);
        subtree<DEPTH + 1, 2 * NODE + 2>(sW, xa, r, acc);
    }
}

// ---------------------------------------------------------------------------
__global__ void __launch_bounds__(TPB, 3)
dtree_kernel(const float* __restrict__ x,
             float* __restrict__ out) {
    __shared__ __align__(16) float sW[NODES_ * 16];   // 16320 B

    for (int i = threadIdx.x; i < NODES_ * 16; i += TPB) sW[i] = g_Wsm[i];
    __syncthreads();

    int row = blockIdx.x * TPB + threadIdx.x;

    // Row features as 16 packed f32x2 (feature pairs), 2x LDG.128.
    u64 xa[16];
    {
        const ulonglong2* pa =
            reinterpret_cast<const ulonglong2*>(x + (size_t)row * F_);
        #pragma unroll
        for (int i = 0; i < 8; ++i) {
            ulonglong2 v = pa[i];
            xa[2 * i] = v.x; xa[2 * i + 1] = v.y;
        }
    }

    float acc = 0.0f;
    subtree<0, 0>(sW, xa, 1.0f, acc);

    out[row] = acc;
}

// ---------------------------------------------------------------------------
extern "C" void kernel_launch(void* const* d_in, const int* in_sizes, int n_in,
                              void* d_out, int out_size) {
    const float* x   = (const float*)d_in[0];   // (N, 32)
    const float* fi  = (const float*)d_in[1];   // (255*32, 1)
    const float* fs  = (const float*)d_in[2];   // (255*32, 1)
    const float* cls = (const float*)d_in[3];   // (256, 1)
    float* out = (float*)d_out;                 // (N, 1) float32

    prep_kernel<<<1, 256>>>(fi, fs, cls);

    // Publish the const blob (async D2D -> graph-capturable, no alloc).
    void* src = nullptr;
    cudaGetSymbolAddress(&src, g_stage);
    cudaMemcpyToSymbolAsync(cD, src, sizeof(CData), 0,
                            cudaMemcpyDeviceToDevice, 0);

    dtree_kernel<<<N_ROWS / TPB, TPB>>>(x, out);
}

// round 10
// speedup vs baseline: 1.0273x; 1.0273x over previous
#include <cuda_runtime.h>
#include <cstdint>

// DTree_84061099917446 — soft decision tree forward pass.
// N=262144 rows, F=32, depth 8, 255 nodes, 256 leaves, C=1.
//
// R10: scalar-FFMA route is pinned at ~166us (fma% stuck at 45 across 4
// designs); move the matvec to the tensor pipe. tcgen05 needs sm_100a, but
// mma.sync.m16n8k8.tf32 (sm_80+) compiles on plain sm_100. Persistent CTAs:
// per 128-row tile, 16 warps compute z = x@W'^T + bias into padded smem via
// tf32 mma with hi/lo split (3 passes, fp32-grade precision), then 4 threads
// per row walk one depth-2 subtree each (literal node ids, register stack),
// and partials are reduced. Gate = EX2+FADD+RCP on y = -log2e*z + log2e*c.

#define F_        32
#define NODES_    255
#define N_ROWS    262144
#define ROWS_T    128
#define NTILES    (N_ROWS / ROWS_T)     // 2048
#define TPB       512
#define GRID_     148
#define LOG2E_F   1.4426950408889634f

typedef unsigned int u32;

// ---- smem layout (byte offsets) ----
#define ZSTRIDE   257                    // floats; conflict-free column walk
#define XSTRIDE   36                     // floats; 16B-aligned, conflict-free
#define WSTRIDE   36
#define SM_Z      0                                   // 128*257*4 = 131584
#define SM_WHI    131584                              // 256*36*4  =  36864
#define SM_WLO    (SM_WHI + 36864)                    // 168448
#define SM_X      (SM_WLO + 36864)                    // 205312 (also pbuf)
#define SM_BIAS   (SM_X + 18432)                      // 223744 (256 f)
#define SM_PR     (SM_BIAS + 1024)                    // 224768 (128 float2)
#define SM_TOTAL  (SM_PR + 1024)                      // 225792 B

// Prologue outputs (scratch via __device__ globals — no allocation).
__device__ __align__(16) float  g_Whi[256 * F_];  // tf32-hi of -log2e*relu(fi)
__device__ __align__(16) float  g_Wlo[256 * F_];  // residual
__device__ float  g_bias[256];                    // +log2e*c (255: 0)
__device__ float2 g_pr[128];                      // (clsR, clsL - clsR)

__device__ __forceinline__ float trunc13(float v) {
    return __uint_as_float(__float_as_uint(v) & 0xFFFFE000u);
}

// ---------------------------------------------------------------------------
// Prologue: one block, 256 threads; thread t handles node t (t=255: pad).
// ---------------------------------------------------------------------------
__global__ void prep_kernel(const float* __restrict__ fi,
                            const float* __restrict__ fs,
                            const float* __restrict__ cls) {
    int t = threadIdx.x;
    if (t < NODES_) {
        float bias = 0.0f;
        #pragma unroll
        for (int f = 0; f < F_; ++f) {
            int idx = t * F_ + f;
            float w = fmaxf(fi[idx], 0.0f);
            float s = 1.0f / (1.0f + expf(-fs[idx]));
            bias += w * s;
            float wp = -LOG2E_F * w;
            float hi = trunc13(wp);
            g_Whi[idx] = hi;
            g_Wlo[idx] = wp - hi;
        }
        g_bias[t] = LOG2E_F * bias;
    } else if (t == NODES_) {
        #pragma unroll
        for (int f = 0; f < F_; ++f) {
            g_Whi[255 * F_ + f] = 0.0f;
            g_Wlo[255 * F_ + f] = 0.0f;
        }
        g_bias[255] = 0.0f;
    }
    if (t < 128) {
        float lv = cls[2 * t];
        float rv = cls[2 * t + 1];
        g_pr[t] = make_float2(rv, lv - rv);
    }
}

// ---------------------------------------------------------------------------
// mma.sync m16n8k8 tf32 (sm_80+): D += A*B, all operands in b32 regs.
// ---------------------------------------------------------------------------
__device__ __forceinline__ void mma8(float (&d)[4], const u32* a, const u32* b) {
    asm volatile(
        "mma.sync.aligned.m16n8k8.row.col.f32.tf32.tf32.f32 "
        "{%0,%1,%2,%3}, {%4,%5,%6,%7}, {%8,%9}, {%0,%1,%2,%3};"
        : "+f"(d[0]), "+f"(d[1]), "+f"(d[2]), "+f"(d[3])
        : "r"(a[0]), "r"(a[1]), "r"(a[2]), "r"(a[3]), "r"(b[0]), "r"(b[1]));
}

// y -> g = sigmoid-equivalent = 1 / (1 + 2^y)
__device__ __forceinline__ float fgate(float y) {
    float e, g;
    asm("ex2.approx.f32 %0, %1;" : "=f"(e) : "f"(y));
    float d = 1.0f + e;
    asm("rcp.approx.f32 %0, %1;" : "=f"(g) : "f"(d));
    return g;
}

// ---------------------------------------------------------------------------
// Register-stack walk of the subtree rooted at NODE (literal), depths 2..7.
// z is pre-biased: zr[n] = -log2e*(x.W_n) + log2e*c_n.
// ---------------------------------------------------------------------------
template<int DEPTH, int NODE>
__device__ __forceinline__ void walk(const float*  __restrict__ zr,
                                     const float2* __restrict__ spr,
                                     float prod, float& acc) {
    float g = fgate(zr[NODE]);
    if constexpr (DEPTH == 7) {
        float2 pr = spr[NODE - 127];              // (clsR, clsL - clsR)
        acc = fmaf(prod, fmaf(g, pr.y, pr.x), acc);
    } else {
        float r = fmaf(-prod, g, prod);           // prod*(1-g)
        walk<DEPTH + 1, 2 * NODE + 1>(zr, spr, prod * g, acc);
        walk<DEPTH + 1, 2 * NODE + 2>(zr, spr, r, acc);
    }
}

// ---------------------------------------------------------------------------
__global__ void __launch_bounds__(TPB, 1)
dtree_kernel(const float* __restrict__ x,
             float* __restrict__ out) {
    extern __shared__ __align__(16) char smem[];
    float*  sz    = reinterpret_cast<float*>(smem + SM_Z);
    float*  sWhi  = reinterpret_cast<float*>(smem + SM_WHI);
    float*  sWlo  = reinterpret_cast<float*>(smem + SM_WLO);
    float*  sx    = reinterpret_cast<float*>(smem + SM_X);
    float*  pbuf  = reinterpret_cast<float*>(smem + SM_X);   // reuse after GEMM
    float*  sbias = reinterpret_cast<float*>(smem + SM_BIAS);
    float2* spr   = reinterpret_cast<float2*>(smem + SM_PR);

    int tid  = threadIdx.x;
    int lane = tid & 31;
    int wrp  = tid >> 5;

    // ---- one-time: W (padded), bias, leaf pairs ----
    for (int i = tid; i < 256 * F_; i += TPB) {
        int n = i >> 5, k = i & 31;
        sWhi[n * WSTRIDE + k] = g_Whi[i];
        sWlo[n * WSTRIDE + k] = g_Wlo[i];
    }
    if (tid < 256) sbias[tid] = g_bias[tid];
    if (tid < 128) spr[tid]   = g_pr[tid];

    int gid = lane >> 2, tig = lane & 3;
    int mbase = (wrp & 7) * 16;
    int nbase = (wrp >> 3) * 128;

    for (int tile = blockIdx.x; tile < NTILES; tile += gridDim.x) {
        __syncthreads();   // pbuf/z reuse from previous tile; first-iter: W ready below

        // ---- stage x tile: 128 rows x 32 floats, padded to stride 36 ----
        const float4* gx = reinterpret_cast<const float4*>(x) + (size_t)tile * 1024;
        for (int i = tid; i < 1024; i += TPB) {
            float4 v = gx[i];
            int r = i >> 3, c = (i & 7) * 4;
            *reinterpret_cast<float4*>(sx + r * XSTRIDE + c) = v;
        }
        __syncthreads();

        // ---- GEMM: warp -> 16 rows x 128 cols, tf32 hi/lo 3-pass ----
        {
            u32 ah[16], al[16];                  // [k*4 + frag]
            #pragma unroll
            for (int k = 0; k < 4; ++k) {
                #pragma unroll
                for (int fr = 0; fr < 4; ++fr) {
                    int r = mbase + gid + (fr & 1) * 8;
                    int c = k * 8 + tig + (fr >> 1) * 4;
                    float v = sx[r * XSTRIDE + c];
                    u32 h = __float_as_uint(v) & 0xFFFFE000u;
                    ah[k * 4 + fr] = h;
                    al[k * 4 + fr] = __float_as_uint(v - __uint_as_float(h));
                }
            }
            #pragma unroll 2
            for (int nt = 0; nt < 16; ++nt) {
                int n0 = nbase + nt * 8;
                float bi0 = sbias[n0 + 2 * tig];
                float bi1 = sbias[n0 + 2 * tig + 1];
                float d[4] = {bi0, bi1, bi0, bi1};     // bias-initialized
                float e[4] = {0.f, 0.f, 0.f, 0.f};
                float f[4] = {0.f, 0.f, 0.f, 0.f};
                u32 bh[8], bl[8];
                #pragma unroll
                for (int k = 0; k < 4; ++k) {
                    int rw = (n0 + gid) * WSTRIDE + k * 8 + tig;
                    bh[k * 2]     = __float_as_uint(sWhi[rw]);
                    bh[k * 2 + 1] = __float_as_uint(sWhi[rw + 4]);
                    bl[k * 2]     = __float_as_uint(sWlo[rw]);
                    bl[k * 2 + 1] = __float_as_uint(sWlo[rw + 4]);
                }
                #pragma unroll
                for (int k = 0; k < 4; ++k) {
                    mma8(d, &ah[k * 4], &bh[k * 2]);   // hi*hi (+bias)
                    mma8(e, &ah[k * 4], &bl[k * 2]);   // hi*lo
                    mma8(f, &al[k * 4], &bh[k * 2]);   // lo*hi
                }
                int r0 = mbase + gid, c0 = n0 + 2 * tig;
                sz[r0 * ZSTRIDE + c0]           = d[0] + e[0] + f[0];
                sz[r0 * ZSTRIDE + c0 + 1]       = d[1] + e[1] + f[1];
                sz[(r0 + 8) * ZSTRIDE + c0]     = d[2] + e[2] + f[2];
                sz[(r0 + 8) * ZSTRIDE + c0 + 1] = d[3] + e[3] + f[3];
            }
        }
        __syncthreads();

        // ---- epilogue: 4 threads per row, one depth-2 subtree each ----
        {
            int row = tid & 127, j = tid >> 7;
            const float* zr = sz + row * ZSTRIDE;
            float g0 = fgate(zr[0]);
            float ga = fgate(zr[1 + (j >> 1)]);
            float p1 = (j & 2) ? (1.0f - g0) : g0;
            float p2 = (j & 1) ? (1.0f - ga) : ga;
            float prod = p1 * p2;
            float acc = 0.0f;
            switch (j) {
                case 0: walk<2, 3>(zr, spr, prod, acc); break;
                case 1: walk<2, 4>(zr, spr, prod, acc); break;
                case 2: walk<2, 5>(zr, spr, prod, acc); break;
                default: walk<2, 6>(zr, spr, prod, acc); break;
            }
            pbuf[tid] = acc;
        }
        __syncthreads();

        if (tid < ROWS_T) {
            float s = (pbuf[tid] + pbuf[tid + 128]) +
                      (pbuf[tid + 256] + pbuf[tid + 384]);
            out[tile * ROWS_T + tid] = s;
        }
    }
}

// ---------------------------------------------------------------------------
extern "C" void kernel_launch(void* const* d_in, const int* in_sizes, int n_in,
                              void* d_out, int out_size) {
    const float* x   = (const float*)d_in[0];   // (N, 32)
    const float* fi  = (const float*)d_in[1];   // (255*32, 1)
    const float* fs  = (const float*)d_in[2];   // (255*32, 1)
    const float* cls = (const float*)d_in[3];   // (256, 1)
    float* out = (float*)d_out;                 // (N, 1) float32

    cudaFuncSetAttribute(dtree_kernel,
                         cudaFuncAttributeMaxDynamicSharedMemorySize, SM_TOTAL);
    prep_kernel<<<1, 256>>>(fi, fs, cls);
    dtree_kernel<<<GRID_, TPB, SM_TOTAL>>>(x, out);
}

// round 11
// speedup vs baseline: 1.0493x; 1.0214x over previous
#include <cuda_runtime.h>
#include <cstdint>

// DTree_84061099917446 — soft decision tree forward pass.
// N=262144 rows, F=32, depth 8, 255 nodes, 256 leaves, C=1.
//
// R11: warp-specialized pipeline. Warps 0-7 produce z = x@W'^T + bias via
// mma.sync.m16n8k8.tf32 (3-pass hi/lo split) into a double-buffered 64-row
// z tile; warps 8-15 concurrently consume the previous tile with the
// register-stack tree walk (4 threads/row, depth-2 subtrees). One bar.sync 0
// per iteration overlaps the phases; consumers reduce via bar.sync 1,256.
// B fragments are pre-packed in mma order (prep kernel) -> 4x LDS.128 per
// 8-column step. A fragments load straight from GMEM.

#define F_        32
#define NODES_    255
#define N_ROWS    262144
#define ROWS_T    64
#define NTILES    (N_ROWS / ROWS_T)     // 4096
#define TPB       512
#define GRID_     148
#define LOG2E_F   1.4426950408889634f

typedef unsigned int u32;

// ---- smem layout (byte offsets) ----
#define ZSTR      257                    // floats; conflict-free column walk
#define SM_Z0     0                      // 64*257*4 = 65792
#define SM_Z1     65792
#define SM_BH     131584                 // 2048 float4 = 32768
#define SM_BL     164352
#define SM_BIAS   197120                 // 256 floats
#define SM_PR     198144                 // 128 float2
#define SM_PBUF   199168                 // 256 floats
#define SM_TOTAL  200192

// Prologue outputs (scratch via __device__ globals — no allocation).
__device__ __align__(16) float4 g_Bfh[2048];   // W'-hi, mma-fragment order
__device__ __align__(16) float4 g_Bfl[2048];   // W'-lo residual
__device__ float  g_bias[256];                 // +log2e*c (idx 255: 0)
__device__ float2 g_pr[128];                   // (clsR, clsL - clsR)

__device__ __forceinline__ float trunc13(float v) {
    return __uint_as_float(__float_as_uint(v) & 0xFFFFE000u);
}

// ---------------------------------------------------------------------------
// Prologue: one block, 256 threads; thread t handles node t (255 = pad).
// Fragment order: lane (gid=n&7, tig) of the consuming warp reads float4s at
// (n>>3)*64 + h*32 + (n&7)*4 + tig, h=0: cols {tig,tig+4,tig+8,tig+12},
// h=1: cols {tig+16,tig+20,tig+24,tig+28}.
// ---------------------------------------------------------------------------
__global__ void prep_kernel(const float* __restrict__ fi,
                            const float* __restrict__ fs,
                            const float* __restrict__ cls) {
    int t = threadIdx.x;
    if (t < 256) {
        float hi[F_], lo[F_];
        float bias = 0.0f;
        #pragma unroll
        for (int f = 0; f < F_; ++f) {
            float wp = 0.0f;
            if (t < NODES_) {
                int idx = t * F_ + f;
                float w = fmaxf(fi[idx], 0.0f);
                float s = 1.0f / (1.0f + expf(-fs[idx]));
                bias += w * s;
                wp = -LOG2E_F * w;
            }
            float h = trunc13(wp);
            hi[f] = h;
            lo[f] = wp - h;
        }
        int base = (t >> 3) * 64 + (t & 7) * 4;
        #pragma unroll
        for (int tig = 0; tig < 4; ++tig) {
            g_Bfh[base + tig] =
                make_float4(hi[tig], hi[tig + 4], hi[tig + 8], hi[tig + 12]);
            g_Bfh[base + 32 + tig] =
                make_float4(hi[tig + 16], hi[tig + 20], hi[tig + 24], hi[tig + 28]);
            g_Bfl[base + tig] =
                make_float4(lo[tig], lo[tig + 4], lo[tig + 8], lo[tig + 12]);
            g_Bfl[base + 32 + tig] =
                make_float4(lo[tig + 16], lo[tig + 20], lo[tig + 24], lo[tig + 28]);
        }
        g_bias[t] = (t < NODES_) ? (LOG2E_F * bias) : 0.0f;
    }
    if (t < 128) {
        float lv = cls[2 * t];
        float rv = cls[2 * t + 1];
        g_pr[t] = make_float2(rv, lv - rv);
    }
}

// ---------------------------------------------------------------------------
__device__ __forceinline__ void mma8(float (&d)[4], const u32* a, const u32* b) {
    asm volatile(
        "mma.sync.aligned.m16n8k8.row.col.f32.tf32.tf32.f32 "
        "{%0,%1,%2,%3}, {%4,%5,%6,%7}, {%8,%9}, {%0,%1,%2,%3};"
        : "+f"(d[0]), "+f"(d[1]), "+f"(d[2]), "+f"(d[3])
        : "r"(a[0]), "r"(a[1]), "r"(a[2]), "r"(a[3]), "r"(b[0]), "r"(b[1]));
}

__device__ __forceinline__ float fgate(float y) {   // 1 / (1 + 2^y)
    float e, g;
    asm("ex2.approx.f32 %0, %1;" : "=f"(e) : "f"(y));
    float d = 1.0f + e;
    asm("rcp.approx.f32 %0, %1;" : "=f"(g) : "f"(d));
    return g;
}

#define CTA_BAR()  asm volatile("barrier.sync 0;" ::: "memory")
#define EPI_BAR()  asm volatile("barrier.sync 1, 256;" ::: "memory")

// ---------------------------------------------------------------------------
// Register-stack walk of the subtree rooted at NODE (literal), depths 2..7.
// ---------------------------------------------------------------------------
template<int DEPTH, int NODE>
__device__ __forceinline__ void walk(const float*  __restrict__ zr,
                                     const float2* __restrict__ spr,
                                     float prod, float& acc) {
    float g = fgate(zr[NODE]);
    if constexpr (DEPTH == 7) {
        float2 pr = spr[NODE - 127];
        acc = fmaf(prod, fmaf(g, pr.y, pr.x), acc);
    } else {
        float r = fmaf(-prod, g, prod);
        walk<DEPTH + 1, 2 * NODE + 1>(zr, spr, prod * g, acc);
        walk<DEPTH + 1, 2 * NODE + 2>(zr, spr, r, acc);
    }
}

// ---------------------------------------------------------------------------
__global__ void __launch_bounds__(TPB, 1)
dtree_kernel(const float* __restrict__ x,
             float* __restrict__ out) {
    extern __shared__ __align__(16) char smem[];
    float4* sBh4  = reinterpret_cast<float4*>(smem + SM_BH);
    float4* sBl4  = reinterpret_cast<float4*>(smem + SM_BL);
    float*  sbias = reinterpret_cast<float*>(smem + SM_BIAS);
    float2* spr   = reinterpret_cast<float2*>(smem + SM_PR);
    float*  pbuf  = reinterpret_cast<float*>(smem + SM_PBUF);

    int tid  = threadIdx.x;
    int lane = tid & 31;
    int wrp  = tid >> 5;
    int bid  = blockIdx.x;
    int nblk = (NTILES - bid + GRID_ - 1) / GRID_;

    // ---- one-time staging (visible after first CTA_BAR) ----
    for (int i = tid; i < 2048; i += TPB) {
        sBh4[i] = g_Bfh[i];
        sBl4[i] = g_Bfl[i];
    }
    if (tid < 256) sbias[tid] = g_bias[tid];
    if (tid < 128) spr[tid]   = g_pr[tid];

    if (wrp < 8) {
        // ================= producers: tf32 GEMM =================
        int gid = lane >> 2, tig = lane & 3;
        int mbase = (wrp & 3) * 16;
        int nbase = (wrp >> 2) * 128;
        for (int step = 0; step <= nblk; ++step) {
            CTA_BAR();
            if (step >= nblk) continue;
            int tile = bid + step * GRID_;
            float* sz = reinterpret_cast<float*>(
                smem + ((step & 1) ? SM_Z1 : SM_Z0));

            // A fragments straight from GMEM, hi/lo split.
            const float* xt = x + (size_t)tile * ROWS_T * F_;
            u32 ah[16], al[16];
            #pragma unroll
            for (int k = 0; k < 4; ++k)
                #pragma unroll
                for (int fr = 0; fr < 4; ++fr) {
                    int r = mbase + gid + (fr & 1) * 8;
                    int c = k * 8 + tig + (fr >> 1) * 4;
                    float v = __ldg(xt + r * F_ + c);
                    u32 h = __float_as_uint(v) & 0xFFFFE000u;
                    ah[k * 4 + fr] = h;
                    al[k * 4 + fr] = __float_as_uint(v - __uint_as_float(h));
                }

            #pragma unroll 2
            for (int nt = 0; nt < 16; ++nt) {
                int n0 = nbase + nt * 8;
                int fb = (n0 >> 3) * 64 + gid * 4 + tig;
                float4 h0 = sBh4[fb], h1 = sBh4[fb + 32];
                float4 l0 = sBl4[fb], l1 = sBl4[fb + 32];
                float2 bi = *reinterpret_cast<const float2*>(
                    sbias + n0 + 2 * tig);
                float d[4] = {bi.x, bi.y, bi.x, bi.y};
                float e[4] = {0.f, 0.f, 0.f, 0.f};
                float f[4] = {0.f, 0.f, 0.f, 0.f};
                u32 bh[8] = {__float_as_uint(h0.x), __float_as_uint(h0.y),
                             __float_as_uint(h0.z), __float_as_uint(h0.w),
                             __float_as_uint(h1.x), __float_as_uint(h1.y),
                             __float_as_uint(h1.z), __float_as_uint(h1.w)};
                u32 bl[8] = {__float_as_uint(l0.x), __float_as_uint(l0.y),
                             __float_as_uint(l0.z), __float_as_uint(l0.w),
                             __float_as_uint(l1.x), __float_as_uint(l1.y),
                             __float_as_uint(l1.z), __float_as_uint(l1.w)};
                #pragma unroll
                for (int k = 0; k < 4; ++k) {
                    mma8(d, &ah[k * 4], &bh[k * 2]);   // hi*hi (+bias)
                    mma8(e, &ah[k * 4], &bl[k * 2]);   // hi*lo
                    mma8(f, &al[k * 4], &bh[k * 2]);   // lo*hi
                }
                int r0 = mbase + gid, c0 = n0 + 2 * tig;
                sz[r0 * ZSTR + c0]           = d[0] + e[0] + f[0];
                sz[r0 * ZSTR + c0 + 1]       = d[1] + e[1] + f[1];
                sz[(r0 + 8) * ZSTR + c0]     = d[2] + e[2] + f[2];
                sz[(r0 + 8) * ZSTR + c0 + 1] = d[3] + e[3] + f[3];
            }
        }
    } else {
        // ================= consumers: tree walk =================
        int etid = tid - 256;
        int row  = etid & 63;
        int j    = etid >> 6;
        for (int step = 0; step <= nblk; ++step) {
            CTA_BAR();
            if (step < 1) continue;
            int tile = bid + (step - 1) * GRID_;
            const float* sz = reinterpret_cast<const float*>(
                smem + (((step - 1) & 1) ? SM_Z1 : SM_Z0));
            const float* zr = sz + row * ZSTR;

            float g0 = fgate(zr[0]);
            float ga = fgate(zr[1 + (j >> 1)]);
            float p1 = (j & 2) ? (1.0f - g0) : g0;
            float p2 = (j & 1) ? (1.0f - ga) : ga;
            float prod = p1 * p2;
            float acc = 0.0f;
            switch (j) {
                case 0:  walk<2, 3>(zr, spr, prod, acc); break;
                case 1:  walk<2, 4>(zr, spr, prod, acc); break;
                case 2:  walk<2, 5>(zr, spr, prod, acc); break;
                default: walk<2, 6>(zr, spr, prod, acc); break;
            }
            pbuf[etid] = acc;
            EPI_BAR();
            if (j == 0) {
                float s = (pbuf[row] + pbuf[row + 64]) +
                          (pbuf[row + 128] + pbuf[row + 192]);
                out[tile * ROWS_T + row] = s;
            }
        }
    }
}

// ---------------------------------------------------------------------------
extern "C" void kernel_launch(void* const* d_in, const int* in_sizes, int n_in,
                              void* d_out, int out_size) {
    const float* x   = (const float*)d_in[0];   // (N, 32)
    const float* fi  = (const float*)d_in[1];   // (255*32, 1)
    const float* fs  = (const float*)d_in[2];   // (255*32, 1)
    const float* cls = (const float*)d_in[3];   // (256, 1)
    float* out = (float*)d_out;                 // (N, 1) float32

    cudaFuncSetAttribute(dtree_kernel,
                         cudaFuncAttributeMaxDynamicSharedMemorySize, SM_TOTAL);
    prep_kernel<<<1, 256>>>(fi, fs, cls);
    dtree_kernel<<<GRID_, TPB, SM_TOTAL>>>(x, out);
}